// round 2
// baseline (speedup 1.0000x reference)
#include <cuda_runtime.h>
#include <cuda_bf16.h>

#define B_    8
#define T_    400
#define U_    60
#define U1_   61
#define E_    256
#define H_    512
#define V_    28
#define BLANK_ 27
#define HC_   64

// Scratch (no cudaMalloc allowed)
__device__ float g_F[B_*T_*H_];        // enc@We + bf   (3200 x 512)
__device__ float g_G[B_*U1_*H_];       // dec@Wd        (488 x 512)
__device__ float g_blank[B_*T_*U1_];   // blank log-probs
__device__ float g_lab[B_*T_*U1_];     // label log-probs (u < 60 valid)

__device__ __forceinline__ float fast_tanh(float x) {
    float y;
    asm("tanh.approx.f32 %0, %1;" : "=f"(y) : "f"(x));
    return y;
}

// ---------------------------------------------------------------------------
// Tiled fp32 GEMM: C[M,N] = A[M,K] @ B[K,N] (+ bias[N]).  64x64 tile, 4x4 micro.
// Requires N % 64 == 0, K % 16 == 0 (N=512, K=256 here). M guarded.
// ---------------------------------------------------------------------------
__global__ void gemm_bias_kernel(const float* __restrict__ A,
                                 const float* __restrict__ Bm,
                                 const float* __restrict__ bias,
                                 float* __restrict__ C,
                                 int M, int N, int K)
{
    __shared__ float As[16][65];   // [k][m], padded vs store conflicts
    __shared__ float Bs[16][64];   // [k][n]
    int tid = threadIdx.x;               // 256 threads
    int tx = tid & 15, ty = tid >> 4;
    int mb = blockIdx.y * 64, nb = blockIdx.x * 64;

    float acc[4][4];
    #pragma unroll
    for (int i = 0; i < 4; i++)
        #pragma unroll
        for (int j = 0; j < 4; j++) acc[i][j] = 0.f;

    for (int k0 = 0; k0 < K; k0 += 16) {
        // Load A tile: 64 rows x 16 k (transposed into As[k][m])
        {
            int r = tid >> 2;              // 0..63  (m within tile)
            int q = (tid & 3) << 2;        // 0,4,8,12 (k within chunk)
            float4 av = make_float4(0.f, 0.f, 0.f, 0.f);
            int gm = mb + r;
            if (gm < M) av = *(const float4*)(A + (size_t)gm * K + k0 + q);
            As[q + 0][r] = av.x; As[q + 1][r] = av.y;
            As[q + 2][r] = av.z; As[q + 3][r] = av.w;
        }
        // Load B tile: 16 k x 64 n
        {
            int rk = tid >> 4;             // 0..15
            int qc = (tid & 15) << 2;      // 0..60
            float4 bv = *(const float4*)(Bm + (size_t)(k0 + rk) * N + nb + qc);
            *(float4*)&Bs[rk][qc] = bv;
        }
        __syncthreads();

        #pragma unroll
        for (int kk = 0; kk < 16; kk++) {
            float a0 = As[kk][ty * 4 + 0];
            float a1 = As[kk][ty * 4 + 1];
            float a2 = As[kk][ty * 4 + 2];
            float a3 = As[kk][ty * 4 + 3];
            float4 b4 = *(float4*)&Bs[kk][tx * 4];
            acc[0][0] = fmaf(a0, b4.x, acc[0][0]);
            acc[0][1] = fmaf(a0, b4.y, acc[0][1]);
            acc[0][2] = fmaf(a0, b4.z, acc[0][2]);
            acc[0][3] = fmaf(a0, b4.w, acc[0][3]);
            acc[1][0] = fmaf(a1, b4.x, acc[1][0]);
            acc[1][1] = fmaf(a1, b4.y, acc[1][1]);
            acc[1][2] = fmaf(a1, b4.z, acc[1][2]);
            acc[1][3] = fmaf(a1, b4.w, acc[1][3]);
            acc[2][0] = fmaf(a2, b4.x, acc[2][0]);
            acc[2][1] = fmaf(a2, b4.y, acc[2][1]);
            acc[2][2] = fmaf(a2, b4.z, acc[2][2]);
            acc[2][3] = fmaf(a2, b4.w, acc[2][3]);
            acc[3][0] = fmaf(a3, b4.x, acc[3][0]);
            acc[3][1] = fmaf(a3, b4.y, acc[3][1]);
            acc[3][2] = fmaf(a3, b4.z, acc[3][2]);
            acc[3][3] = fmaf(a3, b4.w, acc[3][3]);
        }
        __syncthreads();
    }

    #pragma unroll
    for (int i = 0; i < 4; i++) {
        int gm = mb + ty * 4 + i;
        if (gm < M) {
            #pragma unroll
            for (int j = 0; j < 4; j++) {
                int gn = nb + tx * 4 + j;
                float bb = bias ? bias[gn] : 0.f;
                C[(size_t)gm * N + gn] = acc[i][j] + bb;
            }
        }
    }
}

// ---------------------------------------------------------------------------
// Fused joint kernel: per cell (b,t,u) compute
//   logits[v] = sum_h tanh(F[b,t,h]+G[b,u,h]) * Wp[h,v] + bp[v]
//   lse = logsumexp_v; emit blank_lp = logits[27]-lse, lab_lp = logits[tgt]-lse.
// Block: (64,4) threads — 4 consecutive t, all 61 u. H chunked by 64 via smem.
// ---------------------------------------------------------------------------
__global__ void joint_kernel(const float* __restrict__ Wp,
                             const float* __restrict__ bp,
                             const int*  __restrict__ targets)
{
    __shared__ float Fs[4][HC_];
    __shared__ float Gs[U1_][HC_ + 4];
    __shared__ float Ws[V_][HC_ + 4];     // Wp transposed: Ws[v][h]
    __shared__ float bps[V_];

    int b  = blockIdx.y;
    int t0 = blockIdx.x * 4;
    int u  = threadIdx.x;                 // 0..63 (active < 61)
    int tl = threadIdx.y;                 // 0..3
    int tid = tl * 64 + u;                // 0..255

    if (tid < V_) bps[tid] = bp[tid];

    const float* Fb = g_F + (size_t)(b * T_ + t0) * H_;
    const float* Gb = g_G + (size_t)b * U1_ * H_;

    float acc[V_];
    #pragma unroll
    for (int v = 0; v < V_; v++) acc[v] = 0.f;

    for (int hc = 0; hc < H_; hc += HC_) {
        // F chunk: 4 x 64 (one element per thread)
        Fs[tid >> 6][tid & 63] = Fb[(size_t)(tid >> 6) * H_ + hc + (tid & 63)];
        // G chunk: 61 x 64 via float4
        for (int i = tid; i < U1_ * (HC_ / 4); i += 256) {
            int r = i / (HC_ / 4);
            int c = (i % (HC_ / 4)) * 4;
            float4 v4 = *(const float4*)(Gb + (size_t)r * H_ + hc + c);
            *(float4*)&Gs[r][c] = v4;
        }
        // Wp^T chunk: 28 x 64
        for (int i = tid; i < V_ * HC_; i += 256) {
            int v = i >> 6;
            int h = i & 63;
            Ws[v][h] = Wp[(size_t)(hc + h) * V_ + v];
        }
        __syncthreads();

        if (u < U1_) {
            #pragma unroll 2
            for (int h = 0; h < HC_; h += 4) {
                float4 f4 = *(const float4*)&Fs[tl][h];
                float4 g4 = *(const float4*)&Gs[u][h];
                float h0 = fast_tanh(f4.x + g4.x);
                float h1 = fast_tanh(f4.y + g4.y);
                float h2 = fast_tanh(f4.z + g4.z);
                float h3 = fast_tanh(f4.w + g4.w);
                #pragma unroll
                for (int v = 0; v < V_; v++) {
                    float4 w = *(const float4*)&Ws[v][h];
                    float s = fmaf(h0, w.x, acc[v]);
                    s = fmaf(h1, w.y, s);
                    s = fmaf(h2, w.z, s);
                    acc[v] = fmaf(h3, w.w, s);
                }
            }
        }
        __syncthreads();
    }

    if (u < U1_) {
        int t = t0 + tl;
        int tgt = (u < U_) ? targets[b * U_ + u] : 0;

        float m = -1e30f;
        #pragma unroll
        for (int v = 0; v < V_; v++) {
            acc[v] += bps[v];
            m = fmaxf(m, acc[v]);
        }
        float s = 0.f;
        #pragma unroll
        for (int v = 0; v < V_; v++) s += __expf(acc[v] - m);
        float lse = m + __logf(s);

        float lv = acc[0];
        #pragma unroll
        for (int v = 1; v < V_; v++)
            if (v == tgt) lv = acc[v];

        size_t idx = (size_t)(b * T_ + t) * U1_ + u;
        g_blank[idx] = acc[BLANK_] - lse;
        if (u < U_) g_lab[idx] = lv - lse;
    }
}

// ---------------------------------------------------------------------------
// Forward-algorithm DP, anti-diagonal wavefront. One block per batch element.
// alpha[t][u] = logaddexp(alpha[t-1][u]+blank[t-1][u], alpha[t][u-1]+lab[t][u-1])
// ---------------------------------------------------------------------------
__global__ void dp_kernel(const int* __restrict__ t_lens,
                          const int* __restrict__ u_lens,
                          float* __restrict__ out)
{
    int b = blockIdx.x;
    int u = threadIdx.x;                  // 64 threads, active < 61
    __shared__ float buf[2][U1_];

    const float* Bp = g_blank + (size_t)b * T_ * U1_;
    const float* Lp = g_lab   + (size_t)b * T_ * U1_;
    int Tl = t_lens[b], Ul = u_lens[b];

    if (u == 0) buf[0][0] = 0.f;          // alpha[0][0] = 0
    __syncthreads();

    for (int d = 1; d <= (T_ - 1) + (U1_ - 1); d++) {
        int cur = d & 1, prev = cur ^ 1;
        int t = d - u;
        if (u < U1_ && t >= 0 && t < T_) {
            float val;
            if (u == 0) {
                val = buf[prev][0] + Bp[(size_t)(t - 1) * U1_];
            } else if (t == 0) {
                val = buf[prev][u - 1] + Lp[u - 1];
            } else {
                float a  = buf[prev][u]     + Bp[(size_t)(t - 1) * U1_ + u];
                float bb = buf[prev][u - 1] + Lp[(size_t)t * U1_ + (u - 1)];
                float mx = fmaxf(a, bb);
                float mn = fminf(a, bb);
                val = mx + __logf(1.f + __expf(mn - mx));
            }
            buf[cur][u] = val;
            if (t == Tl - 1 && u == Ul)
                out[b] = -(val + Bp[(size_t)t * U1_ + u]);
        }
        __syncthreads();
    }
}

// ---------------------------------------------------------------------------
extern "C" void kernel_launch(void* const* d_in, const int* in_sizes, int n_in,
                              void* d_out, int out_size)
{
    const float* enc     = (const float*)d_in[0];   // (8,400,256)
    const float* dec     = (const float*)d_in[1];   // (8,61,256)
    const float* We      = (const float*)d_in[2];   // (256,512)
    const float* Wd      = (const float*)d_in[3];   // (256,512)
    const float* bf      = (const float*)d_in[4];   // (512,)
    const float* Wp      = (const float*)d_in[5];   // (512,28)
    const float* bp      = (const float*)d_in[6];   // (28,)
    const int*   targets = (const int*)d_in[7];     // (8,60)
    const int*   t_lens  = (const int*)d_in[8];     // (8,)
    const int*   u_lens  = (const int*)d_in[9];     // (8,)
    float* out = (float*)d_out;

    float *pF = nullptr, *pG = nullptr;
    cudaGetSymbolAddress((void**)&pF, g_F);
    cudaGetSymbolAddress((void**)&pG, g_G);

    // F = enc@We + bf : M=3200, N=512, K=256
    gemm_bias_kernel<<<dim3(H_ / 64, (B_ * T_ + 63) / 64), 256>>>(
        enc, We, bf, pF, B_ * T_, H_, E_);
    // G = dec@Wd : M=488, N=512, K=256
    gemm_bias_kernel<<<dim3(H_ / 64, (B_ * U1_ + 63) / 64), 256>>>(
        dec, Wd, nullptr, pG, B_ * U1_, H_, E_);
    // Fused joint + log-softmax gather
    joint_kernel<<<dim3(T_ / 4, B_), dim3(64, 4)>>>(Wp, bp, targets);
    // Forward DP
    dp_kernel<<<B_, 64>>>(t_lens, u_lens, out);
}

// round 3
// speedup vs baseline: 1.9155x; 1.9155x over previous
#include <cuda_runtime.h>
#include <cuda_bf16.h>

#define B_    8
#define T_    400
#define U_    60
#define U1_   61
#define E_    256
#define H_    512
#define V_    28
#define VP_   14          // V/2 packed pairs
#define BLANK_ 27
#define HC_   64
#define NEGF  (-1e30f)

// Scratch (no cudaMalloc allowed)
__device__ float g_F[B_*T_*H_];        // enc@We + bf   (3200 x 512)
__device__ float g_G[B_*U1_*H_];       // dec@Wd        (488 x 512)
__device__ float g_blank[B_*T_*U1_];   // blank log-probs
__device__ float g_lab[B_*T_*U1_];     // label log-probs (u < 60 valid)

__device__ __forceinline__ float fast_tanh(float x) {
    float y;
    asm("tanh.approx.f32 %0, %1;" : "=f"(y) : "f"(x));
    return y;
}
__device__ __forceinline__ unsigned long long pack2(float x, float y) {
    unsigned long long r;
    asm("mov.b64 %0, {%1, %2};" : "=l"(r) : "f"(x), "f"(y));
    return r;
}
__device__ __forceinline__ void unpack2(unsigned long long v, float& x, float& y) {
    asm("mov.b64 {%0, %1}, %2;" : "=f"(x), "=f"(y) : "l"(v));
}
__device__ __forceinline__ unsigned long long fma2(unsigned long long a,
                                                   unsigned long long b,
                                                   unsigned long long c) {
    unsigned long long d;
    asm("fma.rn.f32x2 %0, %1, %2, %3;" : "=l"(d) : "l"(a), "l"(b), "l"(c));
    return d;
}

// ---------------------------------------------------------------------------
// Tiled fp32 GEMM: C[M,N] = A[M,K] @ B[K,N] (+ bias[N]).  64x64 tile, 4x4 micro.
// ---------------------------------------------------------------------------
__global__ void gemm_bias_kernel(const float* __restrict__ A,
                                 const float* __restrict__ Bm,
                                 const float* __restrict__ bias,
                                 float* __restrict__ C,
                                 int M, int N, int K)
{
    __shared__ float As[16][65];
    __shared__ float Bs[16][64];
    int tid = threadIdx.x;               // 256 threads
    int tx = tid & 15, ty = tid >> 4;
    int mb = blockIdx.y * 64, nb = blockIdx.x * 64;

    float acc[4][4];
    #pragma unroll
    for (int i = 0; i < 4; i++)
        #pragma unroll
        for (int j = 0; j < 4; j++) acc[i][j] = 0.f;

    for (int k0 = 0; k0 < K; k0 += 16) {
        {
            int r = tid >> 2;
            int q = (tid & 3) << 2;
            float4 av = make_float4(0.f, 0.f, 0.f, 0.f);
            int gm = mb + r;
            if (gm < M) av = *(const float4*)(A + (size_t)gm * K + k0 + q);
            As[q + 0][r] = av.x; As[q + 1][r] = av.y;
            As[q + 2][r] = av.z; As[q + 3][r] = av.w;
        }
        {
            int rk = tid >> 4;
            int qc = (tid & 15) << 2;
            float4 bv = *(const float4*)(Bm + (size_t)(k0 + rk) * N + nb + qc);
            *(float4*)&Bs[rk][qc] = bv;
        }
        __syncthreads();

        #pragma unroll
        for (int kk = 0; kk < 16; kk++) {
            float a0 = As[kk][ty * 4 + 0];
            float a1 = As[kk][ty * 4 + 1];
            float a2 = As[kk][ty * 4 + 2];
            float a3 = As[kk][ty * 4 + 3];
            float4 b4 = *(float4*)&Bs[kk][tx * 4];
            acc[0][0] = fmaf(a0, b4.x, acc[0][0]);
            acc[0][1] = fmaf(a0, b4.y, acc[0][1]);
            acc[0][2] = fmaf(a0, b4.z, acc[0][2]);
            acc[0][3] = fmaf(a0, b4.w, acc[0][3]);
            acc[1][0] = fmaf(a1, b4.x, acc[1][0]);
            acc[1][1] = fmaf(a1, b4.y, acc[1][1]);
            acc[1][2] = fmaf(a1, b4.z, acc[1][2]);
            acc[1][3] = fmaf(a1, b4.w, acc[1][3]);
            acc[2][0] = fmaf(a2, b4.x, acc[2][0]);
            acc[2][1] = fmaf(a2, b4.y, acc[2][1]);
            acc[2][2] = fmaf(a2, b4.z, acc[2][2]);
            acc[2][3] = fmaf(a2, b4.w, acc[2][3]);
            acc[3][0] = fmaf(a3, b4.x, acc[3][0]);
            acc[3][1] = fmaf(a3, b4.y, acc[3][1]);
            acc[3][2] = fmaf(a3, b4.z, acc[3][2]);
            acc[3][3] = fmaf(a3, b4.w, acc[3][3]);
        }
        __syncthreads();
    }

    #pragma unroll
    for (int i = 0; i < 4; i++) {
        int gm = mb + ty * 4 + i;
        if (gm < M) {
            #pragma unroll
            for (int j = 0; j < 4; j++) {
                int gn = nb + tx * 4 + j;
                float bb = bias ? bias[gn] : 0.f;
                C[(size_t)gm * N + gn] = acc[i][j] + bb;
            }
        }
    }
}

// ---------------------------------------------------------------------------
// Fused joint kernel with packed f32x2 FMA and t-blocking x2.
// Block (64,4): u = threadIdx.x (0..60 active), tl = threadIdx.y.
// Each thread computes 2 t rows: t0+tl and t0+tl+4. Block covers 8 t rows.
// ---------------------------------------------------------------------------
__global__ void joint_kernel(const float* __restrict__ Wp,
                             const float* __restrict__ bp,
                             const int*  __restrict__ targets)
{
    __shared__ float Fs[8][HC_];
    __shared__ float Gs[U1_][HC_ + 4];
    __shared__ unsigned long long Ws2[HC_][VP_];   // {Wp[h][2p], Wp[h][2p+1]}
    __shared__ float bps[V_];

    int b  = blockIdx.y;
    int t0 = blockIdx.x * 8;
    int u  = threadIdx.x;                 // 0..63
    int tl = threadIdx.y;                 // 0..3
    int tid = tl * 64 + u;                // 0..255

    if (tid < V_) bps[tid] = bp[tid];

    const float* Fb = g_F + (size_t)(b * T_ + t0) * H_;
    const float* Gb = g_G + (size_t)b * U1_ * H_;

    unsigned long long acc2[2][VP_];
    #pragma unroll
    for (int r = 0; r < 2; r++)
        #pragma unroll
        for (int p = 0; p < VP_; p++) acc2[r][p] = 0ull;

    for (int hc = 0; hc < H_; hc += HC_) {
        // F chunk: 8 rows x 64 (128 float4 loads)
        if (tid < 128) {
            int r = tid >> 4;
            int c = (tid & 15) << 2;
            *(float4*)&Fs[r][c] = *(const float4*)(Fb + (size_t)r * H_ + hc + c);
        }
        // G chunk: 61 x 64 via float4
        for (int i = tid; i < U1_ * (HC_ / 4); i += 256) {
            int r = i / (HC_ / 4);
            int c = (i % (HC_ / 4)) * 4;
            *(float4*)&Gs[r][c] = *(const float4*)(Gb + (size_t)r * H_ + hc + c);
        }
        // Wp packed: 64 h-rows x 14 float2 (consecutive v pairs)
        for (int i = tid; i < HC_ * VP_; i += 256) {
            int h = i / VP_;
            int p = i % VP_;
            float2 w = *(const float2*)(Wp + (size_t)(hc + h) * V_ + 2 * p);
            Ws2[h][p] = pack2(w.x, w.y);
        }
        __syncthreads();

        if (u < U1_) {
            #pragma unroll 4
            for (int h = 0; h < HC_; h += 4) {
                float4 fa = *(const float4*)&Fs[tl][h];
                float4 fb = *(const float4*)&Fs[tl + 4][h];
                float4 g4 = *(const float4*)&Gs[u][h];
                #pragma unroll
                for (int j = 0; j < 4; j++) {
                    float gj = (j == 0) ? g4.x : (j == 1) ? g4.y : (j == 2) ? g4.z : g4.w;
                    float faj = (j == 0) ? fa.x : (j == 1) ? fa.y : (j == 2) ? fa.z : fa.w;
                    float fbj = (j == 0) ? fb.x : (j == 1) ? fb.y : (j == 2) ? fb.z : fb.w;
                    float tha = fast_tanh(faj + gj);
                    float thb = fast_tanh(fbj + gj);
                    unsigned long long hha = pack2(tha, tha);
                    unsigned long long hhb = pack2(thb, thb);
                    #pragma unroll
                    for (int p = 0; p < VP_; p++) {
                        unsigned long long w = Ws2[h + j][p];
                        acc2[0][p] = fma2(hha, w, acc2[0][p]);
                        acc2[1][p] = fma2(hhb, w, acc2[1][p]);
                    }
                }
            }
        }
        __syncthreads();
    }

    if (u < U1_) {
        int tgt = (u < U_) ? targets[b * U_ + u] : 0;
        #pragma unroll
        for (int r = 0; r < 2; r++) {
            int t = t0 + tl + 4 * r;
            float logits[V_];
            #pragma unroll
            for (int p = 0; p < VP_; p++)
                unpack2(acc2[r][p], logits[2 * p], logits[2 * p + 1]);

            float m = -1e30f;
            #pragma unroll
            for (int v = 0; v < V_; v++) {
                logits[v] += bps[v];
                m = fmaxf(m, logits[v]);
            }
            float s = 0.f;
            #pragma unroll
            for (int v = 0; v < V_; v++) s += __expf(logits[v] - m);
            float lse = m + __logf(s);

            float lv = logits[0];
            #pragma unroll
            for (int v = 1; v < V_; v++)
                if (v == tgt) lv = logits[v];

            size_t idx = (size_t)(b * T_ + t) * U1_ + u;
            g_blank[idx] = logits[BLANK_] - lse;
            if (u < U_) g_lab[idx] = lv - lse;
        }
    }
}

// ---------------------------------------------------------------------------
// Forward-algorithm DP. One block per batch. 1024 threads stage blank/lab
// into smem; warp 0 runs the anti-diagonal wavefront entirely in registers
// with shfl neighbor exchange (no barriers in the recurrence).
// ---------------------------------------------------------------------------
__global__ void dp_kernel(const int* __restrict__ t_lens,
                          const int* __restrict__ u_lens,
                          float* __restrict__ out)
{
    extern __shared__ float sm[];
    float* sB = sm;                      // T_*U1_
    float* sL = sm + T_ * U1_;           // T_*U1_

    int b   = blockIdx.x;
    int tid = threadIdx.x;               // 1024

    const float4* srcB = (const float4*)(g_blank + (size_t)b * T_ * U1_);
    const float4* srcL = (const float4*)(g_lab   + (size_t)b * T_ * U1_);
    const int n4 = T_ * U1_ / 4;         // 6100
    float4* dB = (float4*)sB;
    float4* dL = (float4*)sL;
    for (int i = tid; i < n4; i += 1024) {
        dB[i] = srcB[i];
        dL[i] = srcL[i];
    }
    __syncthreads();
    if (tid >= 32) return;

    const int lane = tid;
    const int Tl = t_lens[b], Ul = u_lens[b];
    const int u_lo = lane, u_hi = lane + 32;

    // diagonal d = 0: alpha[0][0] = 0
    float a_lo = (lane == 0) ? 0.f : NEGF;
    float a_hi = NEGF;

    for (int d = 1; d <= (T_ - 1) + (U1_ - 1); d++) {
        // neighbor (u-1) alphas from previous diagonal
        float p_lo  = __shfl_up_sync(0xffffffffu, a_lo, 1);
        float p_hi  = __shfl_up_sync(0xffffffffu, a_hi, 1);
        float lo31  = __shfl_sync(0xffffffffu, a_lo, 31);
        if (lane == 0) p_hi = lo31;

        float n_lo = NEGF, n_hi = NEGF;
        {
            int t = d - u_lo;
            if (t >= 0 && t < T_) {
                float v1 = (t >= 1)    ? a_lo + sB[(t - 1) * U1_ + u_lo] : NEGF;
                float v2 = (u_lo >= 1) ? p_lo + sL[t * U1_ + u_lo - 1]   : NEGF;
                float mx = fmaxf(v1, v2), mn = fminf(v1, v2);
                n_lo = mx + __logf(1.f + __expf(mn - mx));
                if (t == Tl - 1 && u_lo == Ul)
                    out[b] = -(n_lo + sB[t * U1_ + u_lo]);
            }
        }
        {
            int t = d - u_hi;
            if (u_hi < U1_ && t >= 0 && t < T_) {
                float v1 = (t >= 1) ? a_hi + sB[(t - 1) * U1_ + u_hi] : NEGF;
                float v2 =            p_hi + sL[t * U1_ + u_hi - 1];
                float mx = fmaxf(v1, v2), mn = fminf(v1, v2);
                n_hi = mx + __logf(1.f + __expf(mn - mx));
                if (t == Tl - 1 && u_hi == Ul)
                    out[b] = -(n_hi + sB[t * U1_ + u_hi]);
            }
        }
        a_lo = n_lo; a_hi = n_hi;
    }
}

// ---------------------------------------------------------------------------
extern "C" void kernel_launch(void* const* d_in, const int* in_sizes, int n_in,
                              void* d_out, int out_size)
{
    const float* enc     = (const float*)d_in[0];
    const float* dec     = (const float*)d_in[1];
    const float* We      = (const float*)d_in[2];
    const float* Wd      = (const float*)d_in[3];
    const float* bf      = (const float*)d_in[4];
    const float* Wp      = (const float*)d_in[5];
    const float* bp      = (const float*)d_in[6];
    const int*   targets = (const int*)d_in[7];
    const int*   t_lens  = (const int*)d_in[8];
    const int*   u_lens  = (const int*)d_in[9];
    float* out = (float*)d_out;

    float *pF = nullptr, *pG = nullptr;
    cudaGetSymbolAddress((void**)&pF, g_F);
    cudaGetSymbolAddress((void**)&pG, g_G);

    static bool attr_set = false;
    const int dp_smem = 2 * T_ * U1_ * sizeof(float);   // 195200 B
    if (!attr_set) {
        cudaFuncSetAttribute(dp_kernel,
                             cudaFuncAttributeMaxDynamicSharedMemorySize, dp_smem);
        attr_set = true;
    }

    gemm_bias_kernel<<<dim3(H_ / 64, (B_ * T_ + 63) / 64), 256>>>(
        enc, We, bf, pF, B_ * T_, H_, E_);
    gemm_bias_kernel<<<dim3(H_ / 64, (B_ * U1_ + 63) / 64), 256>>>(
        dec, Wd, nullptr, pG, B_ * U1_, H_, E_);
    joint_kernel<<<dim3(T_ / 8, B_), dim3(64, 4)>>>(Wp, bp, targets);
    dp_kernel<<<B_, 1024, dp_smem>>>(t_lens, u_lens, out);
}

// round 4
// speedup vs baseline: 2.2093x; 1.1534x over previous
#include <cuda_runtime.h>
#include <cuda_bf16.h>

#define B_    8
#define T_    400
#define U_    60
#define U1_   61
#define E_    256
#define H_    512
#define V_    28
#define VP_   14          // V/2 packed pairs
#define BLANK_ 27
#define HC_   64
#define NEGF  (-1e30f)
#define LOG2E 1.4426950408889634f
#define LN2   0.6931471805599453f

// Scratch (no cudaMalloc allowed)
__device__ float g_F[B_*T_*H_];        // enc@We + bf   (3200 x 512)
__device__ float g_G[B_*U1_*H_];       // dec@Wd        (488 x 512)
__device__ float g_blank[B_*T_*U1_];   // blank log-probs
__device__ float g_lab[B_*T_*U1_];     // label log-probs (u < 60 valid)

__device__ __forceinline__ float fast_tanh(float x) {
    float y;
    asm("tanh.approx.f32 %0, %1;" : "=f"(y) : "f"(x));
    return y;
}
__device__ __forceinline__ unsigned long long pack2(float x, float y) {
    unsigned long long r;
    asm("mov.b64 %0, {%1, %2};" : "=l"(r) : "f"(x), "f"(y));
    return r;
}
__device__ __forceinline__ void unpack2(unsigned long long v, float& x, float& y) {
    asm("mov.b64 {%0, %1}, %2;" : "=f"(x), "=f"(y) : "l"(v));
}
__device__ __forceinline__ unsigned long long fma2(unsigned long long a,
                                                   unsigned long long b,
                                                   unsigned long long c) {
    unsigned long long d;
    asm("fma.rn.f32x2 %0, %1, %2, %3;" : "=l"(d) : "l"(a), "l"(b), "l"(c));
    return d;
}

// ---------------------------------------------------------------------------
// Tiled fp32 GEMM: C[M,N] = A[M,K] @ B[K,N] (+ bias[N]).  64x64 tile, 4x4 micro.
// ---------------------------------------------------------------------------
__global__ void gemm_bias_kernel(const float* __restrict__ A,
                                 const float* __restrict__ Bm,
                                 const float* __restrict__ bias,
                                 float* __restrict__ C,
                                 int M, int N, int K)
{
    __shared__ float As[16][65];
    __shared__ float Bs[16][64];
    int tid = threadIdx.x;               // 256 threads
    int tx = tid & 15, ty = tid >> 4;
    int mb = blockIdx.y * 64, nb = blockIdx.x * 64;

    float acc[4][4];
    #pragma unroll
    for (int i = 0; i < 4; i++)
        #pragma unroll
        for (int j = 0; j < 4; j++) acc[i][j] = 0.f;

    for (int k0 = 0; k0 < K; k0 += 16) {
        {
            int r = tid >> 2;
            int q = (tid & 3) << 2;
            float4 av = make_float4(0.f, 0.f, 0.f, 0.f);
            int gm = mb + r;
            if (gm < M) av = *(const float4*)(A + (size_t)gm * K + k0 + q);
            As[q + 0][r] = av.x; As[q + 1][r] = av.y;
            As[q + 2][r] = av.z; As[q + 3][r] = av.w;
        }
        {
            int rk = tid >> 4;
            int qc = (tid & 15) << 2;
            float4 bv = *(const float4*)(Bm + (size_t)(k0 + rk) * N + nb + qc);
            *(float4*)&Bs[rk][qc] = bv;
        }
        __syncthreads();

        #pragma unroll
        for (int kk = 0; kk < 16; kk++) {
            float a0 = As[kk][ty * 4 + 0];
            float a1 = As[kk][ty * 4 + 1];
            float a2 = As[kk][ty * 4 + 2];
            float a3 = As[kk][ty * 4 + 3];
            float4 b4 = *(float4*)&Bs[kk][tx * 4];
            acc[0][0] = fmaf(a0, b4.x, acc[0][0]);
            acc[0][1] = fmaf(a0, b4.y, acc[0][1]);
            acc[0][2] = fmaf(a0, b4.z, acc[0][2]);
            acc[0][3] = fmaf(a0, b4.w, acc[0][3]);
            acc[1][0] = fmaf(a1, b4.x, acc[1][0]);
            acc[1][1] = fmaf(a1, b4.y, acc[1][1]);
            acc[1][2] = fmaf(a1, b4.z, acc[1][2]);
            acc[1][3] = fmaf(a1, b4.w, acc[1][3]);
            acc[2][0] = fmaf(a2, b4.x, acc[2][0]);
            acc[2][1] = fmaf(a2, b4.y, acc[2][1]);
            acc[2][2] = fmaf(a2, b4.z, acc[2][2]);
            acc[2][3] = fmaf(a2, b4.w, acc[2][3]);
            acc[3][0] = fmaf(a3, b4.x, acc[3][0]);
            acc[3][1] = fmaf(a3, b4.y, acc[3][1]);
            acc[3][2] = fmaf(a3, b4.z, acc[3][2]);
            acc[3][3] = fmaf(a3, b4.w, acc[3][3]);
        }
        __syncthreads();
    }

    #pragma unroll
    for (int i = 0; i < 4; i++) {
        int gm = mb + ty * 4 + i;
        if (gm < M) {
            #pragma unroll
            for (int j = 0; j < 4; j++) {
                int gn = nb + tx * 4 + j;
                float bb = bias ? bias[gn] : 0.f;
                C[(size_t)gm * N + gn] = acc[i][j] + bb;
            }
        }
    }
}

// ---------------------------------------------------------------------------
// Fused joint kernel, packed f32x2 FMA, t-blocking x4.
// Block (64,2): u = threadIdx.x (0..60 active), tl = threadIdx.y.
// Each thread computes 4 t rows: t0 + tl + 2*r (r=0..3). Block covers 8 rows.
// ---------------------------------------------------------------------------
__global__ void __launch_bounds__(128)
joint_kernel(const float* __restrict__ Wp,
             const float* __restrict__ bp,
             const int*  __restrict__ targets)
{
    __shared__ float Fs[8][HC_];
    __shared__ float Gs[U1_][HC_ + 4];
    __shared__ unsigned long long Ws2[HC_][VP_];   // {Wp[h][2p], Wp[h][2p+1]}
    __shared__ float bps[V_];

    int b  = blockIdx.y;
    int t0 = blockIdx.x * 8;
    int u  = threadIdx.x;                 // 0..63
    int tl = threadIdx.y;                 // 0..1
    int tid = tl * 64 + u;                // 0..127

    if (tid < V_) bps[tid] = bp[tid];

    const float* Fb = g_F + (size_t)(b * T_ + t0) * H_;
    const float* Gb = g_G + (size_t)b * U1_ * H_;

    unsigned long long acc2[4][VP_];
    #pragma unroll
    for (int r = 0; r < 4; r++)
        #pragma unroll
        for (int p = 0; p < VP_; p++) acc2[r][p] = 0ull;

    for (int hc = 0; hc < H_; hc += HC_) {
        // F chunk: 8 rows x 64 = 128 float4 (one per thread)
        {
            int r = tid >> 4;
            int c = (tid & 15) << 2;
            *(float4*)&Fs[r][c] = *(const float4*)(Fb + (size_t)r * H_ + hc + c);
        }
        // G chunk: 61 x 64 via float4
        for (int i = tid; i < U1_ * (HC_ / 4); i += 128) {
            int r = i / (HC_ / 4);
            int c = (i % (HC_ / 4)) * 4;
            *(float4*)&Gs[r][c] = *(const float4*)(Gb + (size_t)r * H_ + hc + c);
        }
        // Wp packed: 64 h-rows x 14 float2 pairs
        for (int i = tid; i < HC_ * VP_; i += 128) {
            int h = i / VP_;
            int p = i % VP_;
            float2 w = *(const float2*)(Wp + (size_t)(hc + h) * V_ + 2 * p);
            Ws2[h][p] = pack2(w.x, w.y);
        }
        __syncthreads();

        if (u < U1_) {
            #pragma unroll 1
            for (int h = 0; h < HC_; h += 4) {
                float4 g4 = *(const float4*)&Gs[u][h];
                float4 f0 = *(const float4*)&Fs[tl][h];
                float4 f1 = *(const float4*)&Fs[tl + 2][h];
                float4 f2 = *(const float4*)&Fs[tl + 4][h];
                float4 f3 = *(const float4*)&Fs[tl + 6][h];
                #pragma unroll
                for (int j = 0; j < 4; j++) {
                    float gj  = (j == 0) ? g4.x : (j == 1) ? g4.y : (j == 2) ? g4.z : g4.w;
                    float a0j = (j == 0) ? f0.x : (j == 1) ? f0.y : (j == 2) ? f0.z : f0.w;
                    float a1j = (j == 0) ? f1.x : (j == 1) ? f1.y : (j == 2) ? f1.z : f1.w;
                    float a2j = (j == 0) ? f2.x : (j == 1) ? f2.y : (j == 2) ? f2.z : f2.w;
                    float a3j = (j == 0) ? f3.x : (j == 1) ? f3.y : (j == 2) ? f3.z : f3.w;
                    float t0v = fast_tanh(a0j + gj);
                    float t1v = fast_tanh(a1j + gj);
                    float t2v = fast_tanh(a2j + gj);
                    float t3v = fast_tanh(a3j + gj);
                    unsigned long long h0 = pack2(t0v, t0v);
                    unsigned long long h1 = pack2(t1v, t1v);
                    unsigned long long h2 = pack2(t2v, t2v);
                    unsigned long long h3 = pack2(t3v, t3v);
                    #pragma unroll
                    for (int p = 0; p < VP_; p++) {
                        unsigned long long w = Ws2[h + j][p];
                        acc2[0][p] = fma2(h0, w, acc2[0][p]);
                        acc2[1][p] = fma2(h1, w, acc2[1][p]);
                        acc2[2][p] = fma2(h2, w, acc2[2][p]);
                        acc2[3][p] = fma2(h3, w, acc2[3][p]);
                    }
                }
            }
        }
        __syncthreads();
    }

    if (u < U1_) {
        int tgt = (u < U_) ? targets[b * U_ + u] : 0;
        #pragma unroll
        for (int r = 0; r < 4; r++) {
            int t = t0 + tl + 2 * r;
            float logits[V_];
            #pragma unroll
            for (int p = 0; p < VP_; p++)
                unpack2(acc2[r][p], logits[2 * p], logits[2 * p + 1]);

            float m = -1e30f;
            #pragma unroll
            for (int v = 0; v < V_; v++) {
                logits[v] += bps[v];
                m = fmaxf(m, logits[v]);
            }
            float s = 0.f;
            #pragma unroll
            for (int v = 0; v < V_; v++) s += __expf(logits[v] - m);
            float lse = m + __logf(s);

            float lv = logits[0];
            #pragma unroll
            for (int v = 1; v < V_; v++)
                if (v == tgt) lv = logits[v];

            size_t idx = (size_t)(b * T_ + t) * U1_ + u;
            g_blank[idx] = logits[BLANK_] - lse;
            if (u < U_) g_lab[idx] = lv - lse;
        }
    }
}

// ---------------------------------------------------------------------------
// Forward DP, branchless wavefront in log2 domain. One block per batch.
// 1024 threads stage lp tables (pre-scaled by log2e) into smem; warp 0 runs
// the 459-step recurrence with shfl neighbor exchange, zero branches in body.
// ---------------------------------------------------------------------------
__global__ void dp_kernel(const int* __restrict__ t_lens,
                          const int* __restrict__ u_lens,
                          float* __restrict__ out)
{
    extern __shared__ float sm[];
    float* sB = sm;                      // T_*U1_   (log2 domain)
    float* sL = sm + T_ * U1_;           // T_*U1_

    int b   = blockIdx.x;
    int tid = threadIdx.x;               // 1024

    const float4* srcB = (const float4*)(g_blank + (size_t)b * T_ * U1_);
    const float4* srcL = (const float4*)(g_lab   + (size_t)b * T_ * U1_);
    const int n4 = T_ * U1_ / 4;         // 6100
    for (int i = tid; i < n4; i += 1024) {
        float4 vb = srcB[i];
        float4 vl = srcL[i];
        vb.x *= LOG2E; vb.y *= LOG2E; vb.z *= LOG2E; vb.w *= LOG2E;
        vl.x *= LOG2E; vl.y *= LOG2E; vl.z *= LOG2E; vl.w *= LOG2E;
        ((float4*)sB)[i] = vb;
        ((float4*)sL)[i] = vl;
    }
    __syncthreads();
    if (tid >= 32) return;

    const int lane = tid;
    const int Tl = t_lens[b], Ul = u_lens[b];
    const int dcap = (Tl - 1) + Ul;
    const bool cap_lo = (Ul < 32) && (lane == Ul);
    const bool cap_hi = (Ul >= 32) && (lane == Ul - 32);

    const int u_lo = lane;                         // 0..31
    const int u_hi = lane + 32;                    // 32..63
    const int ulo_m1 = max(u_lo - 1, 0);
    const int uhi_c  = min(u_hi, U1_ - 1);
    const int uhi_m1 = min(u_hi - 1, U1_ - 1);

    float a_lo = (lane == 0) ? 0.f : NEGF;
    float a_hi = NEGF;
    float res  = 0.f;

    #pragma unroll 2
    for (int d = 1; d <= (T_ - 1) + (U1_ - 1); d++) {
        float p_lo = __shfl_up_sync(0xffffffffu, a_lo, 1);
        float p_hi = __shfl_up_sync(0xffffffffu, a_hi, 1);
        float lo31 = __shfl_sync(0xffffffffu, a_lo, 31);
        p_lo = (lane == 0) ? NEGF : p_lo;
        p_hi = (lane == 0) ? lo31 : p_hi;

        // lo cell: u = u_lo, t = d - u_lo
        int t  = d - u_lo;
        int i1 = min(max(t - 1, 0), T_ - 1);
        int i2 = min(max(t, 0), T_ - 1);
        float v1 = a_lo + sB[i1 * U1_ + u_lo];
        float v2 = p_lo + sL[i2 * U1_ + ulo_m1];
        float mx = fmaxf(v1, v2), mn = fminf(v1, v2);
        float n_lo = mx + __log2f(1.f + exp2f(mn - mx));

        // hi cell: u = u_hi, t = d - u_hi
        int th = d - u_hi;
        int j1 = min(max(th - 1, 0), T_ - 1);
        int j2 = min(max(th, 0), T_ - 1);
        float w1 = a_hi + sB[j1 * U1_ + uhi_c];
        float w2 = p_hi + sL[j2 * U1_ + uhi_m1];
        float mxh = fmaxf(w1, w2), mnh = fminf(w1, w2);
        float n_hi = mxh + __log2f(1.f + exp2f(mnh - mxh));

        bool hit = (d == dcap);
        res = (hit && cap_lo) ? n_lo : res;
        res = (hit && cap_hi) ? n_hi : res;
        a_lo = n_lo;
        a_hi = n_hi;
    }

    if (cap_lo || cap_hi) {
        float blank_fin = g_blank[(size_t)b * T_ * U1_ + (size_t)(Tl - 1) * U1_ + Ul];
        out[b] = -(res * LN2 + blank_fin);
    }
}

// ---------------------------------------------------------------------------
extern "C" void kernel_launch(void* const* d_in, const int* in_sizes, int n_in,
                              void* d_out, int out_size)
{
    const float* enc     = (const float*)d_in[0];
    const float* dec     = (const float*)d_in[1];
    const float* We      = (const float*)d_in[2];
    const float* Wd      = (const float*)d_in[3];
    const float* bf      = (const float*)d_in[4];
    const float* Wp      = (const float*)d_in[5];
    const float* bp      = (const float*)d_in[6];
    const int*   targets = (const int*)d_in[7];
    const int*   t_lens  = (const int*)d_in[8];
    const int*   u_lens  = (const int*)d_in[9];
    float* out = (float*)d_out;

    float *pF = nullptr, *pG = nullptr;
    cudaGetSymbolAddress((void**)&pF, g_F);
    cudaGetSymbolAddress((void**)&pG, g_G);

    static bool attr_set = false;
    const int dp_smem = 2 * T_ * U1_ * sizeof(float);   // 195200 B
    if (!attr_set) {
        cudaFuncSetAttribute(dp_kernel,
                             cudaFuncAttributeMaxDynamicSharedMemorySize, dp_smem);
        attr_set = true;
    }

    gemm_bias_kernel<<<dim3(H_ / 64, (B_ * T_ + 63) / 64), 256>>>(
        enc, We, bf, pF, B_ * T_, H_, E_);
    gemm_bias_kernel<<<dim3(H_ / 64, (B_ * U1_ + 63) / 64), 256>>>(
        dec, Wd, nullptr, pG, B_ * U1_, H_, E_);
    joint_kernel<<<dim3(T_ / 8, B_), dim3(64, 2)>>>(Wp, bp, targets);
    dp_kernel<<<B_, 1024, dp_smem>>>(t_lens, u_lens, out);
}